// round 1
// baseline (speedup 1.0000x reference)
#include <cuda_runtime.h>

#define N_NODES 50000
#define CH      256
#define N_EDGES 800000
#define NPB     64   // nodes per block in reduction

// ---------------- scratch (device globals; no allocation allowed) -------------
__device__ float g_xw [N_NODES * CH];   // x @ conv_w
__device__ float g_agg[N_NODES * CH];   // scattered aggregation
__device__ float g_deg[N_NODES];        // degree, then dinv in place
__device__ float g_s  [CH];             // sum over nodes of relu(...)

// ---------------- init: zero agg, deg=1 (self loop), s=0 ----------------------
__global__ void k_init() {
    int i = blockIdx.x * blockDim.x + threadIdx.x;
    const int total4 = N_NODES * CH / 4;
    if (i < total4) ((float4*)g_agg)[i] = make_float4(0.f, 0.f, 0.f, 0.f);
    if (i < N_NODES) g_deg[i] = 1.0f;
    if (i < CH)      g_s[i]   = 0.0f;
}

// ---------------- degree count over src ---------------------------------------
__global__ void k_deg(const int* __restrict__ src) {
    int e = blockIdx.x * blockDim.x + threadIdx.x;
    if (e < N_EDGES) atomicAdd(&g_deg[src[e]], 1.0f);
}

__global__ void k_dinv() {
    int i = blockIdx.x * blockDim.x + threadIdx.x;
    if (i < N_NODES) g_deg[i] = rsqrtf(g_deg[i]);   // deg >= 1 always
}

// ---------------- SGEMM: g_xw[M,256] = x[M,256] @ W[256,256] ------------------
#define BM 128
#define BN 128
#define BK 8
__global__ void __launch_bounds__(256) k_gemm(const float* __restrict__ A,
                                              const float* __restrict__ W) {
    __shared__ float As[BK][BM];
    __shared__ float Bs[BK][BN];
    const int tid = threadIdx.x;
    const int bm = blockIdx.x * BM;
    const int bn = blockIdx.y * BN;

    const int a_row = tid >> 1;          // 0..127
    const int a_col = (tid & 1) << 2;    // 0 or 4
    const int b_row = tid >> 5;          // 0..7
    const int b_col = (tid & 31) << 2;   // 0..124

    const int ty = (tid >> 4) << 3;      // 0..120 step 8
    const int tx = (tid & 15) << 3;

    float acc[8][8];
    #pragma unroll
    for (int i = 0; i < 8; i++)
        #pragma unroll
        for (int j = 0; j < 8; j++) acc[i][j] = 0.f;

    for (int k0 = 0; k0 < CH; k0 += BK) {
        float4 av = make_float4(0.f, 0.f, 0.f, 0.f);
        int gr = bm + a_row;
        if (gr < N_NODES) av = *(const float4*)&A[gr * CH + k0 + a_col];
        As[a_col + 0][a_row] = av.x;
        As[a_col + 1][a_row] = av.y;
        As[a_col + 2][a_row] = av.z;
        As[a_col + 3][a_row] = av.w;
        *(float4*)&Bs[b_row][b_col] =
            *(const float4*)&W[(k0 + b_row) * CH + bn + b_col];
        __syncthreads();
        #pragma unroll
        for (int k = 0; k < BK; k++) {
            float ar[8], br[8];
            #pragma unroll
            for (int i = 0; i < 8; i++) ar[i] = As[k][ty + i];
            #pragma unroll
            for (int j = 0; j < 8; j++) br[j] = Bs[k][tx + j];
            #pragma unroll
            for (int i = 0; i < 8; i++)
                #pragma unroll
                for (int j = 0; j < 8; j++) acc[i][j] += ar[i] * br[j];
        }
        __syncthreads();
    }
    #pragma unroll
    for (int i = 0; i < 8; i++) {
        int gr = bm + ty + i;
        if (gr < N_NODES) {
            *(float4*)&g_xw[gr * CH + bn + tx] =
                make_float4(acc[i][0], acc[i][1], acc[i][2], acc[i][3]);
            *(float4*)&g_xw[gr * CH + bn + tx + 4] =
                make_float4(acc[i][4], acc[i][5], acc[i][6], acc[i][7]);
        }
    }
}

// ---------------- edge scatter: agg[dst] += dinv[src]*dinv[dst]*xw[src] -------
// 64 threads per edge, each handles one float4 chunk; vector red to L2.
__global__ void k_scatter(const int* __restrict__ src, const int* __restrict__ dst) {
    long long idx = (long long)blockIdx.x * blockDim.x + threadIdx.x;
    int e = (int)(idx >> 6);
    if (e >= N_EDGES) return;
    int c = ((int)idx & 63) << 2;
    int s = src[e];
    int d = dst[e];
    float coef = g_deg[s] * g_deg[d];   // g_deg holds dinv now
    float4 v = *(const float4*)&g_xw[s * CH + c];
    float* p = &g_agg[d * CH + c];
    asm volatile("red.global.add.v4.f32 [%0], {%1, %2, %3, %4};"
                 :: "l"(p), "f"(coef * v.x), "f"(coef * v.y),
                    "f"(coef * v.z), "f"(coef * v.w)
                 : "memory");
}

// ---------------- h = relu(agg + dinv^2*xw + b); s = sum over nodes -----------
__global__ void __launch_bounds__(256) k_hsum(const float* __restrict__ conv_b) {
    const int c = threadIdx.x;           // channel, 0..255
    const float b = conv_b[c];
    float local = 0.f;
    const int n0 = blockIdx.x * NPB;
    #pragma unroll 4
    for (int i = 0; i < NPB; i++) {
        int n = n0 + i;
        if (n < N_NODES) {
            float di = g_deg[n];
            float v = g_agg[n * CH + c] + di * di * g_xw[n * CH + c] + b;
            local += fmaxf(v, 0.f);
        }
    }
    atomicAdd(&g_s[c], local);
}

// ---------------- 4 tanh GEMVs: out = tanh(s @ w.T + b) -----------------------
__global__ void k_gemv(const float* __restrict__ fc1w, const float* __restrict__ fc1b,
                       const float* __restrict__ fc2w, const float* __restrict__ fc2b,
                       const float* __restrict__ fc3w, const float* __restrict__ fc3b,
                       const float* __restrict__ fc4w, const float* __restrict__ fc4b,
                       float* __restrict__ out) {
    __shared__ float ss[CH];
    const int t = threadIdx.x;           // 0..767
    if (t < CH) ss[t] = g_s[t];
    __syncthreads();

    const float* w; const float* bb; int row;
    if (t < 256)      { w = fc1w; bb = fc1b; row = t; }
    else if (t < 512) { w = fc2w; bb = fc2b; row = t - 256; }
    else if (t < 640) { w = fc3w; bb = fc3b; row = t - 512; }
    else              { w = fc4w; bb = fc4b; row = t - 640; }

    float acc = bb[row];
    const float4* wr = (const float4*)(w + row * CH);
    #pragma unroll
    for (int k = 0; k < CH / 4; k++) {
        float4 wv = wr[k];
        acc += ss[4 * k + 0] * wv.x + ss[4 * k + 1] * wv.y +
               ss[4 * k + 2] * wv.z + ss[4 * k + 3] * wv.w;
    }
    out[t] = tanhf(acc);
}

// ---------------- launch --------------------------------------------------------
extern "C" void kernel_launch(void* const* d_in, const int* in_sizes, int n_in,
                              void* d_out, int out_size) {
    const float* x      = (const float*)d_in[0];
    const int*   ei     = (const int*)  d_in[1];
    const float* conv_w = (const float*)d_in[2];
    const float* conv_b = (const float*)d_in[3];
    const float* fc1w   = (const float*)d_in[4];
    const float* fc1b   = (const float*)d_in[5];
    const float* fc2w   = (const float*)d_in[6];
    const float* fc2b   = (const float*)d_in[7];
    const float* fc3w   = (const float*)d_in[8];
    const float* fc3b   = (const float*)d_in[9];
    const float* fc4w   = (const float*)d_in[10];
    const float* fc4b   = (const float*)d_in[11];
    float* out = (float*)d_out;

    const int* src = ei;            // edge_index[0]
    const int* dst = ei + N_EDGES;  // edge_index[1]

    k_init<<<(N_NODES * CH / 4 + 255) / 256, 256>>>();
    k_deg<<<(N_EDGES + 255) / 256, 256>>>(src);
    k_dinv<<<(N_NODES + 255) / 256, 256>>>();

    dim3 gg((N_NODES + BM - 1) / BM, CH / BN);
    k_gemm<<<gg, 256>>>(x, conv_w);

    // 800000 edges * 64 threads = 51,200,000 threads = 200000 blocks of 256
    k_scatter<<<(int)(((long long)N_EDGES * 64 + 255) / 256), 256>>>(src, dst);

    k_hsum<<<(N_NODES + NPB - 1) / NPB, 256>>>(conv_b);

    k_gemv<<<1, 768>>>(fc1w, fc1b, fc2w, fc2b, fc3w, fc3b, fc4w, fc4b, out);
}